// round 12
// baseline (speedup 1.0000x reference)
#include <cuda_runtime.h>

// ---------------------------------------------------------------------------
// R12: R11 body (2 rows/warp, integer ladder, epilogue short-circuit) with
// finer block granularity to shave the wave-quantization tail.
//
// Floor decomposition (R6-R11): elapsed = launch/distribution overhead
// (~5us at un-boosted clock) + exposed addr->gather chain + issue term +
// wave tail. Issue term is exhausted (R11: -50% inst => -2% time). Last
// structural knob: 512 blocks/148 SMs = 3.46 (13% straggler tail) -> 2048
// blocks of 64 threads = 13.8/SM (<=7% tail), same 4096 warps.
//
// Reference semantics (verified R2-R11, rel_err 3.279e-6):
//  * value = |mem[b, addr[b]]| exactly (eq_gate is an exact one-hot).
//  * floor(v/10^p) == unsigned /10 ladder on u = (unsigned)v  (v < 2^24).
//  * n = 1 + #{p in 1..5 : q_p != 0}.
//  * qmax clipping per pos {999,101,11,2,1,1} (reference loop break).
//  * cutoff bands (quot = qmax*st near v = (qmax+1)*d - 0.5): soft fallback.
//  * pos 0 soft 4-term ascending sum when v < 1001: soft fallback.
// ---------------------------------------------------------------------------

static __device__ __forceinline__ float sigm(float z) {
    return __fdividef(1.0f, 1.0f + __expf(-z));
}
// silu_threshold(x) = (silu(20x+10) - silu(20x-10)) / 20
static __device__ __forceinline__ float st_fast(float x) {
    float z1 = __fmaf_rn(20.0f, x, 10.0f);
    float z2 = __fmaf_rn(20.0f, x, -10.0f);
    return (z1 * sigm(z1) - z2 * sigm(z2)) * 0.05f;
}
// reference digit = floor(quot - floor(quot/10)*10); handles negative quot.
static __device__ __forceinline__ int mod10_digit(float quot) {
    return (int)floorf(quot - floorf(quot * 0.1f) * 10.0f);
}

// token for output column with offset j = col - op:
// digit token for j < n, newline for j == n, else 0.
static __device__ __forceinline__ float token_at(int j, int n, unsigned pk) {
    int pi = n - 1 - j;
    pi = pi < 0 ? 0 : (pi > 5 ? 5 : pi);
    float g = (float)((pk >> (pi * 4)) & 15u);
    return (j >= 0 && j < n) ? (48.0f + g) : ((j == n) ? 10.0f : 0.0f);
}

__global__ void __launch_bounds__(64)
c4_printf_2r_kernel(const float* __restrict__ mem,
                    const int*   __restrict__ addr,
                    const int*   __restrict__ outp,
                    float*       __restrict__ out,
                    int B, int M) {
    const unsigned FULL = 0xFFFFFFFFu;
    int lane = threadIdx.x & 31;
    int warp = (blockIdx.x * blockDim.x + threadIdx.x) >> 5;
    int base = warp * 2;                 // rows base, base+1
    if (base >= B) return;

    // --- owner phase: lanes 0..1 each own one row ------------------------------
    int  myrow = base + lane;
    bool owner = (lane < 2) && (myrow < B);

    float    v   = 0.0f;
    int      op  = 0;
    unsigned pkn = 0;                    // nibble digits | (n << 24)

    if (owner) {
        int a = __ldg(addr + myrow);
        op    = __ldg(outp + myrow);
        v     = fabsf(__ldg(mem + myrow * M + a));   // MLP=2 in one LDG

        // unsigned integer digit ladder (exact; v < 2^24)
        unsigned u  = (unsigned)v;
        unsigned q1 = u  / 10u;
        unsigned q2 = q1 / 10u;
        unsigned q3 = q2 / 10u;
        unsigned q4 = q3 / 10u;
        unsigned q5 = q4 / 10u;

        unsigned d1 = (q1 <= 101u) ? (q1 - 10u * q2) : 0u;
        unsigned d2 = (q2 <= 11u)  ? (q2 - 10u * q3) : 0u;
        unsigned d3 = (q3 <= 2u)   ? (q3 - 10u * q4) : 0u;
        unsigned d4 = (q4 <= 1u)   ? q4 : 0u;
        unsigned d5 = (q5 <= 1u)   ? q5 : 0u;

        int n = 1 + (q1 != 0u) + (q2 != 0u) + (q3 != 0u)
                  + (q4 != 0u) + (q5 != 0u);

        // qmax cutoff bands (~0.03% of rows)
        if (v > 1018.0f && v < 20001.0f) {
            if (fabsf(v - 1019.5f) < 1.41f) {
                float g = 1019.5f - v;
                float s = (g > -1.4011f) ? st_fast(g) : 0.0f;
                d1 = (unsigned)mod10_digit(101.0f * s);
            } else if (fabsf(v - 1199.5f) < 1.41f) {
                float g = 1199.5f - v;
                float s = (g > -1.4011f) ? st_fast(g) : 0.0f;
                d2 = (unsigned)mod10_digit(11.0f * s);
            } else if (fabsf(v - 2999.5f) < 1.41f) {
                float g = 2999.5f - v;
                float s = (g > -1.4011f) ? st_fast(g) : 0.0f;
                d3 = (unsigned)mod10_digit(2.0f * s);
            } else if (fabsf(v - 19999.5f) < 1.41f) {
                float g = 19999.5f - v;
                float s = (g > -1.4011f) ? st_fast(g) : 0.0f;
                d4 = (unsigned)mod10_digit(1.0f * s);
            }
        }

        // pos 0: soft 4-term ascending sum (per-lane serial; ~1% of rows)
        unsigned d0 = 0u;
        if (v < 1001.0f) {
            int qlo = (int)floorf(v - 1.93f) + 1;
            float quot = 0.0f;
            #pragma unroll
            for (int k = 0; k < 4; ++k) {
                int q = qlo + k;
                if (q >= 0 && q <= 999) {
                    float qf = (float)q;
                    float a1 = v - qf + 0.5f;        // lower gate arg (d = 1)
                    float a2 = qf + 0.5f - v;        // upper gate arg
                    quot += st_fast(a1) * st_fast(a2) * qf;
                }
            }
            d0 = (unsigned)mod10_digit(quot);
        }

        pkn = d0 | (d1 << 4) | (d2 << 8) | (d3 << 12)
            | (d4 << 16) | (d5 << 20) | ((unsigned)n << 24);
    }

    // --- epilogue: 2 rows, 2 coalesced 128B stores each --------------------------
    #pragma unroll
    for (int r = 0; r < 2; ++r) {
        int row = base + r;
        if (row >= B) break;
        unsigned pk = __shfl_sync(FULL, pkn, r);
        int      o  = __shfl_sync(FULL, op,  r);
        float    vv = __shfl_sync(FULL, v,   r);
        int nn = (int)(pk >> 24);

        // tokens occupy columns o..o+n (n <= 6): each 32-col half is live
        // only for a narrow op range — skip the dead half's select chain.
        float t0 = 0.0f, t1 = 0.0f;
        if (o <= 37)  t0 = token_at(lane - o, nn, pk);        // cols 0..31
        if (o >= 26)  t1 = token_at(lane + 32 - o, nn, pk);   // cols 32..63

        float* orow = out + row * 65;
        orow[lane]      = t0;
        orow[lane + 32] = t1;
        if (lane == 0) orow[64] = vv;    // appended value column (exact)
    }
}

extern "C" void kernel_launch(void* const* d_in, const int* in_sizes, int n_in,
                              void* d_out, int out_size) {
    const float* mem  = (const float*)d_in[0];   // [B, M] fp32
    const int*   addr = (const int*)d_in[1];     // [B] int32
    const int*   outp = (const int*)d_in[2];     // [B] int32
    float*       out  = (float*)d_out;           // [B, 65] fp32

    int B = in_sizes[1];
    int M = in_sizes[0] / B;

    // 2 rows per warp, 2 warps per block -> 4 rows per block, 2048 blocks:
    // 13.8 blocks/SM minimizes wave-quantization tail (same 4096 warps).
    int rows_per_block = 4;
    int blocks = (B + rows_per_block - 1) / rows_per_block;
    c4_printf_2r_kernel<<<blocks, 64>>>(mem, addr, outp, out, B, M);
}